// round 7
// baseline (speedup 1.0000x reference)
#include <cuda_runtime.h>
#include <cuda_bf16.h>
#include <math.h>

// Problem constants
#define TT   256
#define BB   64
#define IDIM 1024
#define HDIM 1024
#define N4   4096            // 4*HDIM, gate-major: col n = g*1024 + h
#define K2   2048            // fused K: [0,1024)=input dim, [1024,2048)=hidden dim

// ---------------- device scratch (static; allocations are banned) -------------
// g_W rows 0..1023   : masked W_x^T  (g_W[k][g*1024+h] = W_x[g][h][k]*mask)
// g_W rows 1024..2047: masked W_h^T
__device__ float g_W[K2 * N4];      // 32 MB
__device__ float g_C[BB * HDIM];    // cell state (updated in place)

// ---------- masked transpose: g_W[row_off+k][g*1024+h] = W[g][h][k]*M[g][h][k] --
__global__ void masked_transpose_kernel(const float* __restrict__ W,
                                        const float* __restrict__ Mk,
                                        int row_off)
{
    __shared__ float tile[32][33];
    const int g  = blockIdx.z;
    const int h0 = blockIdx.y * 32;
    const int k0 = blockIdx.x * 32;
    const int tx = threadIdx.x;   // 32
    const int ty = threadIdx.y;   // 8

    #pragma unroll
    for (int j = 0; j < 32; j += 8) {
        int idx = (g * HDIM + h0 + ty + j) * 1024 + k0 + tx;  // < 4.2M, fits int
        tile[ty + j][tx] = W[idx] * Mk[idx];
    }
    __syncthreads();
    #pragma unroll
    for (int j = 0; j < 32; j += 8) {
        int k = k0 + ty + j;
        int h = h0 + tx;
        g_W[(row_off + k) * N4 + g * HDIM + h] = tile[tx][ty + j];
    }
}

// ---------------- init cell state from C0 ------------------------------------
__global__ void init_c_kernel(const float* __restrict__ C0)
{
    int i = (blockIdx.x * blockDim.x + threadIdx.x) * 4;  // 64*256*4 = 65536
    float4 v = *(const float4*)&C0[i];
    *(float4*)&g_C[i] = v;
}

// ---------------- fused recurrent step ----------------------------------------
// One launch per t. grid = 128 CTAs (8 h-columns each -> 32 gate-cols),
// block = 256 threads. Each thread: 2 batch rows x 4 cols, K loop over 2048
// (first 1024 from X_t, second 1024 from H_prev). Per k: LDS.64 + LDS.128
// feeding 8 FFMA; per-SM FFMA issue = 32 cyc/k (binding), LDS well under cap.
#define KT 32
__global__ void __launch_bounds__(256)
lstm_step_kernel(const float* __restrict__ Xt,      // [64][1024]
                 const float* __restrict__ Hprev,   // [64][1024]
                 const float* __restrict__ bias,    // [4096] (g*1024+h)
                 float* __restrict__ Hout)          // [64][1024]
{
    __shared__ float Hs[KT][64];     // A tile transposed: Hs[k][b]
    __shared__ float Ws[KT][32];     // 32 cols = g*8 + hh
    __shared__ float preS[64 * 32];  // pre-activations [b][g*8+hh]

    const int tid  = threadIdx.x;
    const int h0   = blockIdx.x * 8;
    const int cg   = tid & 7;        // col group: cols cg*4 .. cg*4+3
    const int bblk = tid >> 3;       // 0..31 : b = bblk*2, bblk*2+1

    float acc[2][4];
    #pragma unroll
    for (int i = 0; i < 2; i++)
        #pragma unroll
        for (int j = 0; j < 4; j++) acc[i][j] = 0.f;

    // A-tile load indices (8 floats per thread: 64 b x 32 k total)
    const int la_b  = tid >> 2;          // 0..63
    const int la_kq = (tid & 3) * 8;     // 0,8,16,24
    // W-tile load indices (float4 per thread: 32 k x 32 cols)
    const int lw_k  = tid >> 3;          // 0..31
    const int lw_c  = (tid & 7) * 4;     // 0..28
    const int lw_g  = lw_c >> 3;         // gate
    const int lw_hh = lw_c & 7;          // h within tile

    for (int k0 = 0; k0 < K2; k0 += KT) {
        const float* Ab = (k0 < IDIM) ? Xt : Hprev;
        const int koff  = k0 & (IDIM - 1);

        // load A tile transposed
        {
            const float* ap = &Ab[la_b * IDIM + koff + la_kq];
            float4 v0 = *(const float4*)&ap[0];
            float4 v1 = *(const float4*)&ap[4];
            Hs[la_kq + 0][la_b] = v0.x; Hs[la_kq + 1][la_b] = v0.y;
            Hs[la_kq + 2][la_b] = v0.z; Hs[la_kq + 3][la_b] = v0.w;
            Hs[la_kq + 4][la_b] = v1.x; Hs[la_kq + 5][la_b] = v1.y;
            Hs[la_kq + 6][la_b] = v1.z; Hs[la_kq + 7][la_b] = v1.w;
        }
        // load W tile
        {
            float4 w = *(const float4*)&g_W[(k0 + lw_k) * N4 + lw_g * HDIM + h0 + lw_hh];
            *(float4*)&Ws[lw_k][lw_c] = w;
        }
        __syncthreads();

        #pragma unroll 8
        for (int kk = 0; kk < KT; kk++) {
            float2 hv = *(const float2*)&Hs[kk][bblk * 2];
            float4 wv = *(const float4*)&Ws[kk][cg * 4];
            acc[0][0] += hv.x * wv.x; acc[0][1] += hv.x * wv.y;
            acc[0][2] += hv.x * wv.z; acc[0][3] += hv.x * wv.w;
            acc[1][0] += hv.y * wv.x; acc[1][1] += hv.y * wv.y;
            acc[1][2] += hv.y * wv.z; acc[1][3] += hv.y * wv.w;
        }
        __syncthreads();
    }

    // stage pre-activations: col c = cg*4+j = g*8+hh
    #pragma unroll
    for (int i = 0; i < 2; i++) {
        int b = bblk * 2 + i;
        #pragma unroll
        for (int j = 0; j < 4; j++)
            preS[b * 32 + cg * 4 + j] = acc[i][j];
    }
    __syncthreads();

    // epilogue: 512 (b,hh) cells / 256 threads = 2 each
    #pragma unroll
    for (int it = 0; it < 2; it++) {
        int idx = tid + it * 256;            // 0..511
        int b   = idx >> 3;
        int hh  = idx & 7;
        int hg  = h0 + hh;
        float pi = preS[b * 32 +  0 + hh] + bias[0 * HDIM + hg];
        float pf = preS[b * 32 +  8 + hh] + bias[1 * HDIM + hg];
        float po = preS[b * 32 + 16 + hh] + bias[2 * HDIM + hg];
        float pc = preS[b * 32 + 24 + hh] + bias[3 * HDIM + hg];

        float ig = 1.f / (1.f + expf(-pi));
        float fg = 1.f / (1.f + expf(-pf));
        float og = 1.f / (1.f + expf(-po));
        float ct = tanhf(pc);

        float cold = g_C[b * HDIM + hg];
        float cnew = fg * cold + ig * ct;
        g_C[b * HDIM + hg]  = cnew;
        Hout[b * HDIM + hg] = og * tanhf(cnew);
    }
}

// ------------------------------- launch ---------------------------------------
extern "C" void kernel_launch(void* const* d_in, const int* in_sizes, int n_in,
                              void* d_out, int out_size)
{
    // Resolve inputs by element count (robust to metadata ordering):
    //   16777216 -> inputs (T,B,I)        4096 -> bias (4,H)
    //   4194304 x4 -> {W_x,W_h,mask_x,mask_h}   65536 x2 -> {H0,C0}
    const float* inputs = nullptr;
    const float* bias   = nullptr;
    const float* bigs[4] = {nullptr, nullptr, nullptr, nullptr};
    const float* sml[2]  = {nullptr, nullptr};
    int nb = 0, ns = 0, inputs_idx = -1;

    for (int i = 0; i < n_in; i++) {
        const float* p = (const float*)d_in[i];
        switch (in_sizes[i]) {
            case TT * BB * IDIM:  inputs = p; inputs_idx = i; break;
            case 4 * HDIM:        bias = p; break;
            case 4 * HDIM * IDIM: if (nb < 4) bigs[nb++] = p; break;
            case BB * HDIM:       if (ns < 2) sml[ns++] = p; break;
            default: break;
        }
    }

    const float *W_x, *W_h, *mask_x, *mask_h, *H0, *C0;
    if (inputs && bias && nb == 4 && ns == 2) {
        // Both insertion order and alphabetical order keep W's before masks and
        // preserve (i-th W <-> i-th mask) pairing. x-vs-h assignment: if inputs
        // is d_in[0] we are in setup_inputs() insertion order (W_x first);
        // otherwise assume alphabetical (W_h first).
        if (inputs_idx == 0) { W_x = bigs[0]; W_h = bigs[1]; mask_x = bigs[2]; mask_h = bigs[3]; }
        else                 { W_h = bigs[0]; W_x = bigs[1]; mask_h = bigs[2]; mask_x = bigs[3]; }
        H0 = sml[0]; C0 = sml[1];
    } else {
        // positional fallback (setup_inputs() dict order)
        inputs = (const float*)d_in[0];
        W_x    = (const float*)d_in[1];
        W_h    = (const float*)d_in[2];
        bias   = (const float*)d_in[3];
        mask_x = (const float*)d_in[4];
        mask_h = (const float*)d_in[5];
        H0     = (const float*)d_in[6];
        C0     = (const float*)d_in[7];
    }

    float* out = (float*)d_out;                   // (T,B,H)

    // 1) masked transposed weights into combined g_W
    dim3 tgrid(32, 32, 4), tblk(32, 8);
    masked_transpose_kernel<<<tgrid, tblk>>>(W_x, mask_x, 0);
    masked_transpose_kernel<<<tgrid, tblk>>>(W_h, mask_h, IDIM);

    // 2) reset cell state
    init_c_kernel<<<64, 256>>>(C0);

    // 3) sequential recurrence (x-projection fused into each step)
    for (int t = 0; t < TT; t++) {
        const float* Xt    = inputs + (size_t)t * BB * IDIM;
        const float* Hprev = (t == 0) ? H0 : (out + (size_t)(t - 1) * BB * HDIM);
        lstm_step_kernel<<<128, 256>>>(Xt, Hprev, bias,
                                       out + (size_t)t * BB * HDIM);
    }
}

// round 9
// speedup vs baseline: 1.0006x; 1.0006x over previous
#include <cuda_runtime.h>
#include <cuda_bf16.h>
#include <math.h>

// Problem constants
#define TT   256
#define BB   64
#define IDIM 1024
#define HDIM 1024
#define N4   4096            // 4*HDIM, gate-major: col n = g*1024 + h
#define K2   2048            // fused K: [0,1024)=input dim, [1024,2048)=hidden dim

// ---------------- device scratch (static; allocations are banned) -------------
// g_W rows 0..1023   : masked W_x^T  (g_W[k][g*1024+h] = W_x[g][h][k]*mask)
// g_W rows 1024..2047: masked W_h^T
__device__ float g_W[K2 * N4];      // 32 MB
__device__ float g_C[BB * HDIM];    // cell state (updated in place)

// ---------- masked transpose: g_W[row_off+k][g*1024+h] = W[g][h][k]*M[g][h][k] --
__global__ void masked_transpose_kernel(const float* __restrict__ W,
                                        const float* __restrict__ Mk,
                                        int row_off)
{
    __shared__ float tile[32][33];
    const int g  = blockIdx.z;
    const int h0 = blockIdx.y * 32;
    const int k0 = blockIdx.x * 32;
    const int tx = threadIdx.x;   // 32
    const int ty = threadIdx.y;   // 8

    #pragma unroll
    for (int j = 0; j < 32; j += 8) {
        int idx = (g * HDIM + h0 + ty + j) * 1024 + k0 + tx;  // < 4.2M, fits int
        tile[ty + j][tx] = W[idx] * Mk[idx];
    }
    __syncthreads();
    #pragma unroll
    for (int j = 0; j < 32; j += 8) {
        int k = k0 + ty + j;
        int h = h0 + tx;
        g_W[(row_off + k) * N4 + g * HDIM + h] = tile[tx][ty + j];
    }
}

// ---------------- init cell state from C0 ------------------------------------
__global__ void init_c_kernel(const float* __restrict__ C0)
{
    int i = (blockIdx.x * blockDim.x + threadIdx.x) * 4;  // 64*256*4 = 65536
    float4 v = *(const float4*)&C0[i];
    *(float4*)&g_C[i] = v;
}

// ---------------- fused recurrent step ----------------------------------------
// One launch per t. grid = 128 CTAs (8 h-columns each -> 32 gate-cols),
// block = 256 threads. Each thread: 2 batch rows x 4 cols, K loop over 2048
// (first 1024 from X_t, second 1024 from H_prev). Per k: LDS.64 + LDS.128
// feeding 8 FFMA; per-SM FFMA issue = 32 cyc/k (binding), LDS well under cap.
#define KT 32
__global__ void __launch_bounds__(256)
lstm_step_kernel(const float* __restrict__ Xt,      // [64][1024]
                 const float* __restrict__ Hprev,   // [64][1024]
                 const float* __restrict__ bias,    // [4096] (g*1024+h)
                 float* __restrict__ Hout)          // [64][1024]
{
    __shared__ float Hs[KT][64];     // A tile transposed: Hs[k][b]
    __shared__ float Ws[KT][32];     // 32 cols = g*8 + hh
    __shared__ float preS[64 * 32];  // pre-activations [b][g*8+hh]

    const int tid  = threadIdx.x;
    const int h0   = blockIdx.x * 8;
    const int cg   = tid & 7;        // col group: cols cg*4 .. cg*4+3
    const int bblk = tid >> 3;       // 0..31 : b = bblk*2, bblk*2+1

    float acc[2][4];
    #pragma unroll
    for (int i = 0; i < 2; i++)
        #pragma unroll
        for (int j = 0; j < 4; j++) acc[i][j] = 0.f;

    // A-tile load indices (8 floats per thread: 64 b x 32 k total)
    const int la_b  = tid >> 2;          // 0..63
    const int la_kq = (tid & 3) * 8;     // 0,8,16,24
    // W-tile load indices (float4 per thread: 32 k x 32 cols)
    const int lw_k  = tid >> 3;          // 0..31
    const int lw_c  = (tid & 7) * 4;     // 0..28
    const int lw_g  = lw_c >> 3;         // gate
    const int lw_hh = lw_c & 7;          // h within tile

    for (int k0 = 0; k0 < K2; k0 += KT) {
        const float* Ab = (k0 < IDIM) ? Xt : Hprev;
        const int koff  = k0 & (IDIM - 1);

        // load A tile transposed
        {
            const float* ap = &Ab[la_b * IDIM + koff + la_kq];
            float4 v0 = *(const float4*)&ap[0];
            float4 v1 = *(const float4*)&ap[4];
            Hs[la_kq + 0][la_b] = v0.x; Hs[la_kq + 1][la_b] = v0.y;
            Hs[la_kq + 2][la_b] = v0.z; Hs[la_kq + 3][la_b] = v0.w;
            Hs[la_kq + 4][la_b] = v1.x; Hs[la_kq + 5][la_b] = v1.y;
            Hs[la_kq + 6][la_b] = v1.z; Hs[la_kq + 7][la_b] = v1.w;
        }
        // load W tile
        {
            float4 w = *(const float4*)&g_W[(k0 + lw_k) * N4 + lw_g * HDIM + h0 + lw_hh];
            *(float4*)&Ws[lw_k][lw_c] = w;
        }
        __syncthreads();

        #pragma unroll 8
        for (int kk = 0; kk < KT; kk++) {
            float2 hv = *(const float2*)&Hs[kk][bblk * 2];
            float4 wv = *(const float4*)&Ws[kk][cg * 4];
            acc[0][0] += hv.x * wv.x; acc[0][1] += hv.x * wv.y;
            acc[0][2] += hv.x * wv.z; acc[0][3] += hv.x * wv.w;
            acc[1][0] += hv.y * wv.x; acc[1][1] += hv.y * wv.y;
            acc[1][2] += hv.y * wv.z; acc[1][3] += hv.y * wv.w;
        }
        __syncthreads();
    }

    // stage pre-activations: col c = cg*4+j = g*8+hh
    #pragma unroll
    for (int i = 0; i < 2; i++) {
        int b = bblk * 2 + i;
        #pragma unroll
        for (int j = 0; j < 4; j++)
            preS[b * 32 + cg * 4 + j] = acc[i][j];
    }
    __syncthreads();

    // epilogue: 512 (b,hh) cells / 256 threads = 2 each
    #pragma unroll
    for (int it = 0; it < 2; it++) {
        int idx = tid + it * 256;            // 0..511
        int b   = idx >> 3;
        int hh  = idx & 7;
        int hg  = h0 + hh;
        float pi = preS[b * 32 +  0 + hh] + bias[0 * HDIM + hg];
        float pf = preS[b * 32 +  8 + hh] + bias[1 * HDIM + hg];
        float po = preS[b * 32 + 16 + hh] + bias[2 * HDIM + hg];
        float pc = preS[b * 32 + 24 + hh] + bias[3 * HDIM + hg];

        float ig = 1.f / (1.f + expf(-pi));
        float fg = 1.f / (1.f + expf(-pf));
        float og = 1.f / (1.f + expf(-po));
        float ct = tanhf(pc);

        float cold = g_C[b * HDIM + hg];
        float cnew = fg * cold + ig * ct;
        g_C[b * HDIM + hg]  = cnew;
        Hout[b * HDIM + hg] = og * tanhf(cnew);
    }
}

// ------------------------------- launch ---------------------------------------
extern "C" void kernel_launch(void* const* d_in, const int* in_sizes, int n_in,
                              void* d_out, int out_size)
{
    // Resolve inputs by element count (robust to metadata ordering):
    //   16777216 -> inputs (T,B,I)        4096 -> bias (4,H)
    //   4194304 x4 -> {W_x,W_h,mask_x,mask_h}   65536 x2 -> {H0,C0}
    const float* inputs = nullptr;
    const float* bias   = nullptr;
    const float* bigs[4] = {nullptr, nullptr, nullptr, nullptr};
    const float* sml[2]  = {nullptr, nullptr};
    int nb = 0, ns = 0, inputs_idx = -1;

    for (int i = 0; i < n_in; i++) {
        const float* p = (const float*)d_in[i];
        switch (in_sizes[i]) {
            case TT * BB * IDIM:  inputs = p; inputs_idx = i; break;
            case 4 * HDIM:        bias = p; break;
            case 4 * HDIM * IDIM: if (nb < 4) bigs[nb++] = p; break;
            case BB * HDIM:       if (ns < 2) sml[ns++] = p; break;
            default: break;
        }
    }

    const float *W_x, *W_h, *mask_x, *mask_h, *H0, *C0;
    if (inputs && bias && nb == 4 && ns == 2) {
        // Both insertion order and alphabetical order keep W's before masks and
        // preserve (i-th W <-> i-th mask) pairing. x-vs-h assignment: if inputs
        // is d_in[0] we are in setup_inputs() insertion order (W_x first);
        // otherwise assume alphabetical (W_h first).
        if (inputs_idx == 0) { W_x = bigs[0]; W_h = bigs[1]; mask_x = bigs[2]; mask_h = bigs[3]; }
        else                 { W_h = bigs[0]; W_x = bigs[1]; mask_h = bigs[2]; mask_x = bigs[3]; }
        H0 = sml[0]; C0 = sml[1];
    } else {
        // positional fallback (setup_inputs() dict order)
        inputs = (const float*)d_in[0];
        W_x    = (const float*)d_in[1];
        W_h    = (const float*)d_in[2];
        bias   = (const float*)d_in[3];
        mask_x = (const float*)d_in[4];
        mask_h = (const float*)d_in[5];
        H0     = (const float*)d_in[6];
        C0     = (const float*)d_in[7];
    }

    float* out = (float*)d_out;                   // (T,B,H)

    // 1) masked transposed weights into combined g_W
    dim3 tgrid(32, 32, 4), tblk(32, 8);
    masked_transpose_kernel<<<tgrid, tblk>>>(W_x, mask_x, 0);
    masked_transpose_kernel<<<tgrid, tblk>>>(W_h, mask_h, IDIM);

    // 2) reset cell state
    init_c_kernel<<<64, 256>>>(C0);

    // 3) sequential recurrence (x-projection fused into each step)
    for (int t = 0; t < TT; t++) {
        const float* Xt    = inputs + (size_t)t * BB * IDIM;
        const float* Hprev = (t == 0) ? H0 : (out + (size_t)(t - 1) * BB * HDIM);
        lstm_step_kernel<<<128, 256>>>(Xt, Hprev, bias,
                                       out + (size_t)t * BB * HDIM);
    }
}